// round 12
// baseline (speedup 1.0000x reference)
#include <cuda_runtime.h>
#include <math.h>
#include <stdio.h>

#define NATOMS 10000
#define NEDGES 64000
#define NB     128
#define NH     600
#define NG     50
#define NL     6
#define LOG2F_C 0.6931471805599453f
#define PI_F    3.14159265358979323846f

// ---------------- scratch (device globals; no allocation allowed) ----------------
__device__ float g_rbf [(size_t)NEDGES * NG];
__device__ float g_Ccut[NEDGES];
__device__ float g_h   [(size_t)NATOMS * NH];
__device__ float g_t1  [(size_t)NEDGES * NH];
__device__ float g_W   [(size_t)NEDGES * NH];
__device__ float g_hp  [(size_t)NATOMS * NH];
__device__ float g_agg [(size_t)NATOMS * NH];
__device__ float g_x   [(size_t)NATOMS * NH];
__device__ float g_pool[(size_t)NB * NH];
__device__ float g_cnt [NB];

__device__ __forceinline__ float ssp(float x) {
    return log1pf(expf(-fabsf(x))) + fmaxf(x, 0.0f) - LOG2F_C;
}

__device__ __forceinline__ float f2tf(float x) {
    unsigned r;
    asm("cvt.rna.tf32.f32 %0, %1;" : "=r"(r) : "f"(x));
    return __uint_as_float(r);
}

__device__ __forceinline__ void mma_tf32(float* c, const unsigned* a, unsigned b0, unsigned b1) {
    asm volatile(
        "mma.sync.aligned.m16n8k8.row.col.f32.tf32.tf32.f32 "
        "{%0,%1,%2,%3}, {%4,%5,%6,%7}, {%8,%9}, {%0,%1,%2,%3};\n"
        : "+f"(c[0]), "+f"(c[1]), "+f"(c[2]), "+f"(c[3])
        : "r"(a[0]), "r"(a[1]), "r"(a[2]), "r"(a[3]), "r"(b0), "r"(b1));
}

__device__ __forceinline__ void ldm_x4(unsigned* r, unsigned addr) {
    asm volatile("ldmatrix.sync.aligned.m8n8.x4.shared.b16 {%0,%1,%2,%3}, [%4];"
                 : "=r"(r[0]), "=r"(r[1]), "=r"(r[2]), "=r"(r[3]) : "r"(addr));
}

// ---------------- edge geometry ----------------
__global__ void edge_geom_kernel(const float* __restrict__ pos,
                                 const int* __restrict__ ei,
                                 float* __restrict__ rbf,
                                 float* __restrict__ Ccut) {
    int e = blockIdx.x * blockDim.x + threadIdx.x;
    if (e >= NEDGES) return;
    int s = ei[e];
    int t = ei[NEDGES + e];
    float dx = pos[3*s+0] - pos[3*t+0];
    float dy = pos[3*s+1] - pos[3*t+1];
    float dz = pos[3*s+2] - pos[3*t+2];
    float d = sqrtf(dx*dx + dy*dy + dz*dz + 1e-12f);
    Ccut[e] = 0.5f * (cosf(d * (PI_F / 10.0f)) + 1.0f);
    const float delta = 10.0f / 49.0f;
    const float coeff = -0.5f / (delta * delta);
    #pragma unroll
    for (int g = 0; g < NG; g++) {
        float u = d - (float)g * delta;
        rbf[(size_t)e * NG + g] = expf(coeff * u * u);
    }
}

// ---------------- h init ----------------
__global__ void init_h_kernel(const int* __restrict__ z,
                              const float* __restrict__ emb,
                              float* __restrict__ h) {
    size_t idx = (size_t)blockIdx.x * blockDim.x + threadIdx.x;
    if (idx >= (size_t)NATOMS * NH) return;
    int n = (int)(idx / NH);
    int c = (int)(idx - (size_t)n * NH);
    h[idx] = emb[(size_t)z[n] * NH + c];
}

// ---------------- TF32 tensor-core GEMM, 128x128x16 tile, ldmatrix A+B -------
// C[M,N] = A[M,K] @ B[K,N], row-major.
// As: [m][k] pitch 20, A fragments via ldmatrix.x4 (conflict-free, 5r mod 8 bijection).
// Bt: [n][k] pitch 20 (B TRANSPOSED in smem), B fragments via ldmatrix.x4:
//   one x4 per nf tile covers both kk-steps (reg j = B[n=g][k=4j+t]).
// B staging: thread loads a k-column quad (4x coalesced LDG.32) and commits
//   one float4 STS along k -> conflict-free ((5n+kq) mod 8 bijection).
// EPI 0: out=v+bias  1: out=ssp(v+bias)  2: out=(v+bias)*rowmul[row]  3: out=v
// EPI 4: acc[row,col] += v+bias  (residual)
#define LDA_S 20
#define LDB_T 20

template<int EPI>
__global__ __launch_bounds__(256, 2)
void gemm_tc(const float* __restrict__ A, const float* __restrict__ Bm,
             const float* __restrict__ bias, float* __restrict__ Cout,
             int M, int Nn, int K,
             const float* __restrict__ rowmul, float* __restrict__ accp)
{
    __shared__ float As[128 * LDA_S];   // [m][k]
    __shared__ float Bt[128 * LDB_T];   // [n][k] transposed

    const int tid  = threadIdx.x;
    const int lane = tid & 31;
    const int warp = tid >> 5;
    const int wm = (warp >> 2) * 64;   // 0/64
    const int wn = (warp &  3) * 32;   // 0/32/64/96
    const int g = lane >> 2;
    const int t = lane & 3;
    const int m0 = blockIdx.y * 128;
    const int n0 = blockIdx.x * 128;

    float acc[4][4][4];
    #pragma unroll
    for (int i = 0; i < 4; i++)
        #pragma unroll
        for (int j = 0; j < 4; j++)
            #pragma unroll
            for (int r = 0; r < 4; r++) acc[i][j][r] = 0.0f;

    const bool kvec = ((K & 3) == 0);
    float4 aReg[2];
    float  bVal[2][4];

    // B staging assignment: idx = tid + i*256 in [0,512): n = idx&127, kq = idx>>7
    const int bN [2] = { tid & 127, tid & 127 };        // same n both halves? no:
    // idx0 = tid -> n = tid&127, kq = tid>>7 (0..1); idx1 = tid+256 -> kq+2
    const int bKq[2] = { tid >> 7, (tid >> 7) + 2 };

    auto loadTile = [&](int kt) {
        #pragma unroll
        for (int i = 0; i < 2; i++) {
            int idx = tid + i * 256;
            int m = idx >> 2, t4 = (idx & 3) << 2;
            int row = m0 + m, col = kt + t4;
            float4 v = make_float4(0.f, 0.f, 0.f, 0.f);
            if (row < M) {
                if (kvec && col + 4 <= K) {
                    v = *(const float4*)&A[(size_t)row * K + col];
                } else {
                    const float* ap = &A[(size_t)row * K];
                    if (col + 0 < K) v.x = ap[col + 0];
                    if (col + 1 < K) v.y = ap[col + 1];
                    if (col + 2 < K) v.z = ap[col + 2];
                    if (col + 3 < K) v.w = ap[col + 3];
                }
            }
            aReg[i] = v;
            // B: 4 scalars down a k-column at fixed n
            int nn = n0 + bN[i];
            int kb = kt + bKq[i] * 4;
            #pragma unroll
            for (int j = 0; j < 4; j++) {
                bVal[i][j] = (nn < Nn && kb + j < K) ? Bm[(size_t)(kb + j) * Nn + nn] : 0.0f;
            }
        }
    };

    auto commitTile = [&]() {
        #pragma unroll
        for (int i = 0; i < 2; i++) {
            int idx = tid + i * 256;
            int m = idx >> 2, t4 = (idx & 3) << 2;
            float4 v = aReg[i];
            v.x = f2tf(v.x); v.y = f2tf(v.y); v.z = f2tf(v.z); v.w = f2tf(v.w);
            *(float4*)&As[m * LDA_S + t4] = v;
            float4 w;
            w.x = f2tf(bVal[i][0]); w.y = f2tf(bVal[i][1]);
            w.z = f2tf(bVal[i][2]); w.w = f2tf(bVal[i][3]);
            *(float4*)&Bt[bN[i] * LDB_T + bKq[i] * 4] = w;
        }
    };

    // A ldmatrix per-lane address: matrices (m0-7,k0-3),(m8-15,k0-3),(m0-7,k4-7),(m8-15,k4-7)
    const int m_lane = wm + ((lane >> 3) & 1) * 8 + (lane & 7);
    const int k_offA = (lane >> 4) * 4;
    const unsigned aSm = (unsigned)__cvta_generic_to_shared(As);
    const unsigned aLaneAddr = aSm + (unsigned)(m_lane * LDA_S + k_offA) * 4u;
    // B ldmatrix per-lane address: matrices j=0..3 = k-quads 0..3 of rows n0-7 (per nf)
    const unsigned bSm = (unsigned)__cvta_generic_to_shared(Bt);
    const unsigned bLaneAddr = bSm +
        (unsigned)((wn + (lane & 7)) * LDB_T + (lane >> 3) * 4) * 4u;

    loadTile(0);

    for (int k0 = 0; k0 < K; k0 += 16) {
        commitTile();
        __syncthreads();

        int kn = k0 + 16;
        if (kn < K) loadTile(kn);

        // B: 4 ldmatrix.x4 cover all 4 nf x both kk steps
        unsigned bfr[4][4];
        #pragma unroll
        for (int nf = 0; nf < 4; nf++)
            ldm_x4(bfr[nf], bLaneAddr + (unsigned)(nf * 8 * LDB_T) * 4u);

        #pragma unroll
        for (int kc = 0; kc < 2; kc++) {
            unsigned af[4][4];
            #pragma unroll
            for (int mf = 0; mf < 4; mf++)
                ldm_x4(af[mf], aLaneAddr + (unsigned)(mf * 16 * LDA_S + kc * 8) * 4u);
            #pragma unroll
            for (int mf = 0; mf < 4; mf++)
                #pragma unroll
                for (int nf = 0; nf < 4; nf++)
                    mma_tf32(acc[mf][nf], af[mf], bfr[nf][kc * 2], bfr[nf][kc * 2 + 1]);
        }
        __syncthreads();
    }

    // epilogue
    #pragma unroll
    for (int mf = 0; mf < 4; mf++) {
        #pragma unroll
        for (int nf = 0; nf < 4; nf++) {
            int rb = m0 + wm + mf * 16 + g;
            int cb = n0 + wn + nf * 8 + 2 * t;
            #pragma unroll
            for (int half = 0; half < 2; half++) {
                int mm = rb + half * 8;
                if (mm >= M) continue;
                float v0 = acc[mf][nf][half * 2 + 0];
                float v1 = acc[mf][nf][half * 2 + 1];
                float cm = (EPI == 2) ? rowmul[mm] : 0.0f;
                #pragma unroll
                for (int q = 0; q < 2; q++) {
                    int nn = cb + q;
                    if (nn >= Nn) continue;
                    float v = (q == 0) ? v0 : v1;
                    if (EPI == 0)      { v += bias[nn]; }
                    else if (EPI == 1) { v = ssp(v + bias[nn]); }
                    else if (EPI == 2) { v = (v + bias[nn]) * cm; }
                    else if (EPI == 4) { accp[(size_t)mm * Nn + nn] += v + bias[nn]; continue; }
                    Cout[(size_t)mm * Nn + nn] = v;
                }
            }
        }
    }
}

// ---------------- CFConv scatter (float4 vectorized) ----------------
__global__ void scatter_kernel(const int* __restrict__ ei,
                               const float* __restrict__ hp,
                               const float* __restrict__ W,
                               float* __restrict__ agg) {
    size_t idx = (size_t)blockIdx.x * blockDim.x + threadIdx.x;
    const int Q = NH / 4;  // 150
    if (idx >= (size_t)NEDGES * Q) return;
    int e = (int)(idx / Q);
    int c4 = (int)(idx - (size_t)e * Q) * 4;
    int s = ei[e];
    int t = ei[NEDGES + e];
    float4 hv = *(const float4*)&hp[(size_t)s * NH + c4];
    float4 wv = *(const float4*)&W[(size_t)e * NH + c4];
    float* dst = &agg[(size_t)t * NH + c4];
    atomicAdd(dst + 0, hv.x * wv.x);
    atomicAdd(dst + 1, hv.y * wv.y);
    atomicAdd(dst + 2, hv.z * wv.z);
    atomicAdd(dst + 3, hv.w * wv.w);
}

// ---------------- pooling ----------------
__global__ void pool_sum_kernel(const int* __restrict__ batch,
                                const float* __restrict__ h,
                                float* __restrict__ psum) {
    size_t idx = (size_t)blockIdx.x * blockDim.x + threadIdx.x;
    const int Q = NH / 4;
    if (idx >= (size_t)NATOMS * Q) return;
    int n = (int)(idx / Q);
    int c4 = (int)(idx - (size_t)n * Q) * 4;
    float4 hv = *(const float4*)&h[(size_t)n * NH + c4];
    float* dst = &psum[(size_t)batch[n] * NH + c4];
    atomicAdd(dst + 0, hv.x);
    atomicAdd(dst + 1, hv.y);
    atomicAdd(dst + 2, hv.z);
    atomicAdd(dst + 3, hv.w);
}

__global__ void pool_cnt_kernel(const int* __restrict__ batch, float* __restrict__ cnt) {
    int n = blockIdx.x * blockDim.x + threadIdx.x;
    if (n >= NATOMS) return;
    atomicAdd(&cnt[batch[n]], 1.0f);
}

__global__ void pool_div_kernel(float* __restrict__ psum, const float* __restrict__ cnt) {
    int idx = blockIdx.x * blockDim.x + threadIdx.x;
    if (idx >= NB * NH) return;
    int b = idx / NH;
    psum[idx] /= fmaxf(cnt[b], 1.0f);
}

// ---------------- host launcher ----------------
extern "C" void kernel_launch(void* const* d_in, const int* in_sizes, int n_in,
                              void* d_out, int out_size) {
    const int*   z        = (const int*)  d_in[0];
    const float* pos      = (const float*)d_in[1];
    const int*   batch    = (const int*)  d_in[2];
    const int*   ei       = (const int*)  d_in[3];
    const float* emb      = (const float*)d_in[4];
    const float* mlp_w1   = (const float*)d_in[5];
    const float* mlp_b1   = (const float*)d_in[6];
    const float* mlp_w2   = (const float*)d_in[7];
    const float* mlp_b2   = (const float*)d_in[8];
    const float* lin1_w   = (const float*)d_in[9];
    const float* lin2_w   = (const float*)d_in[10];
    const float* lin2_b   = (const float*)d_in[11];
    const float* int_lin_w = (const float*)d_in[12];
    const float* int_lin_b = (const float*)d_in[13];
    const float* pool_w   = (const float*)d_in[14];
    const float* pool_b   = (const float*)d_in[15];
    float* out = (float*)d_out;

    float *p_rbf, *p_C, *p_h, *p_t1, *p_W, *p_hp, *p_agg, *p_x, *p_pool, *p_cnt;
    cudaGetSymbolAddress((void**)&p_rbf,  g_rbf);
    cudaGetSymbolAddress((void**)&p_C,    g_Ccut);
    cudaGetSymbolAddress((void**)&p_h,    g_h);
    cudaGetSymbolAddress((void**)&p_t1,   g_t1);
    cudaGetSymbolAddress((void**)&p_W,    g_W);
    cudaGetSymbolAddress((void**)&p_hp,   g_hp);
    cudaGetSymbolAddress((void**)&p_agg,  g_agg);
    cudaGetSymbolAddress((void**)&p_x,    g_x);
    cudaGetSymbolAddress((void**)&p_pool, g_pool);
    cudaGetSymbolAddress((void**)&p_cnt,  g_cnt);

    edge_geom_kernel<<<(NEDGES + 255) / 256, 256>>>(pos, ei, p_rbf, p_C);
    {
        size_t tot = (size_t)NATOMS * NH;
        init_h_kernel<<<(unsigned)((tot + 255) / 256), 256>>>(z, emb, p_h);
    }

    dim3 blk(256);
    dim3 gE((NH + 127) / 128, (NEDGES + 127) / 128);
    dim3 gN((NH + 127) / 128, (NATOMS + 127) / 128);
    dim3 gB((NH + 127) / 128, (NB + 127) / 128);

    for (int k = 0; k < NL; k++) {
        const float* w1  = mlp_w1 + (size_t)k * NG * NH;
        const float* b1  = mlp_b1 + (size_t)k * NH;
        const float* w2  = mlp_w2 + (size_t)k * NH * NH;
        const float* b2  = mlp_b2 + (size_t)k * NH;
        const float* l1  = lin1_w + (size_t)k * NH * NH;
        const float* l2  = lin2_w + (size_t)k * NH * NH;
        const float* l2b = lin2_b + (size_t)k * NH;
        const float* il  = int_lin_w + (size_t)k * NH * NH;
        const float* ilb = int_lin_b + (size_t)k * NH;

        // t1 = ssp(rbf @ w1 + b1)           [E,H]
        gemm_tc<1><<<gE, blk>>>(p_rbf, w1, b1, p_t1, NEDGES, NH, NG, nullptr, nullptr);
        // W = (t1 @ w2 + b2) * C[:,None]    [E,H]
        gemm_tc<2><<<gE, blk>>>(p_t1, w2, b2, p_W, NEDGES, NH, NH, p_C, nullptr);
        // hp = h @ lin1                     [N,H]
        gemm_tc<3><<<gN, blk>>>(p_h, l1, nullptr, p_hp, NATOMS, NH, NH, nullptr, nullptr);
        // agg = scatter_add(hp[src] * W, dst)
        cudaMemsetAsync(p_agg, 0, (size_t)NATOMS * NH * sizeof(float));
        {
            size_t tot = (size_t)NEDGES * (NH / 4);
            scatter_kernel<<<(unsigned)((tot + 255) / 256), 256>>>(ei, p_hp, p_W, p_agg);
        }
        // x = ssp(agg @ lin2 + lin2_b)      [N,H]
        gemm_tc<1><<<gN, blk>>>(p_agg, l2, l2b, p_x, NATOMS, NH, NH, nullptr, nullptr);
        // h += x @ int_lin + int_lin_b      [N,H]
        gemm_tc<4><<<gN, blk>>>(p_x, il, ilb, nullptr, NATOMS, NH, NH, nullptr, p_h);
    }

    cudaMemsetAsync(p_pool, 0, (size_t)NB * NH * sizeof(float));
    cudaMemsetAsync(p_cnt, 0, NB * sizeof(float));
    {
        size_t tot = (size_t)NATOMS * (NH / 4);
        pool_sum_kernel<<<(unsigned)((tot + 255) / 256), 256>>>(batch, p_h, p_pool);
    }
    pool_cnt_kernel<<<(NATOMS + 255) / 256, 256>>>(batch, p_cnt);
    pool_div_kernel<<<(NB * NH + 255) / 256, 256>>>(p_pool, p_cnt);

    // out = pooled @ pool_w + pool_b       [B,H]
    gemm_tc<0><<<gB, blk>>>(p_pool, pool_w, pool_b, out, NB, NH, NH, nullptr, nullptr);
}

// round 15
// speedup vs baseline: 1.7812x; 1.7812x over previous
#include <cuda_runtime.h>
#include <cuda_fp16.h>
#include <math.h>
#include <stdio.h>

#define NATOMS 10000
#define NEDGES 64000
#define NB     128
#define NH     600
#define NG     50
#define NL     6
#define LOG2F_C 0.6931471805599453f
#define PI_F    3.14159265358979323846f

// ---------------- scratch (device globals; no allocation allowed) ----------------
__device__ float g_rbf [(size_t)NEDGES * NG];
__device__ float g_Ccut[NEDGES];
__device__ float g_h   [(size_t)NATOMS * NH];
__device__ float g_t1  [(size_t)NEDGES * NH];
__device__ float g_W   [(size_t)NEDGES * NH];
__device__ float g_hp  [(size_t)NATOMS * NH];
__device__ float g_agg [(size_t)NATOMS * NH];
__device__ float g_x   [(size_t)NATOMS * NH];
__device__ float g_pool[(size_t)NB * NH];
__device__ float g_cnt [NB];

__device__ __forceinline__ float ssp(float x) {
    return log1pf(expf(-fabsf(x))) + fmaxf(x, 0.0f) - LOG2F_C;
}

// fp16 MMA m16n8k16, fp32 accumulate
__device__ __forceinline__ void mma_f16(float* c, const unsigned* a, unsigned b0, unsigned b1) {
    asm volatile(
        "mma.sync.aligned.m16n8k16.row.col.f32.f16.f16.f32 "
        "{%0,%1,%2,%3}, {%4,%5,%6,%7}, {%8,%9}, {%0,%1,%2,%3};\n"
        : "+f"(c[0]), "+f"(c[1]), "+f"(c[2]), "+f"(c[3])
        : "r"(a[0]), "r"(a[1]), "r"(a[2]), "r"(a[3]), "r"(b0), "r"(b1));
}

__device__ __forceinline__ void ldm_x4(unsigned* r, unsigned addr) {
    asm volatile("ldmatrix.sync.aligned.m8n8.x4.shared.b16 {%0,%1,%2,%3}, [%4];"
                 : "=r"(r[0]), "=r"(r[1]), "=r"(r[2]), "=r"(r[3]) : "r"(addr));
}

__device__ __forceinline__ void ldm_x4_t(unsigned* r, unsigned addr) {
    asm volatile("ldmatrix.sync.aligned.m8n8.x4.trans.shared.b16 {%0,%1,%2,%3}, [%4];"
                 : "=r"(r[0]), "=r"(r[1]), "=r"(r[2]), "=r"(r[3]) : "r"(addr));
}

__device__ __forceinline__ unsigned pack_h2(float x, float y) {
    __half2 h = __floats2half2_rn(x, y);
    return *(unsigned*)&h;
}

// ---------------- edge geometry ----------------
__global__ void edge_geom_kernel(const float* __restrict__ pos,
                                 const int* __restrict__ ei,
                                 float* __restrict__ rbf,
                                 float* __restrict__ Ccut) {
    int e = blockIdx.x * blockDim.x + threadIdx.x;
    if (e >= NEDGES) return;
    int s = ei[e];
    int t = ei[NEDGES + e];
    float dx = pos[3*s+0] - pos[3*t+0];
    float dy = pos[3*s+1] - pos[3*t+1];
    float dz = pos[3*s+2] - pos[3*t+2];
    float d = sqrtf(dx*dx + dy*dy + dz*dz + 1e-12f);
    Ccut[e] = 0.5f * (cosf(d * (PI_F / 10.0f)) + 1.0f);
    const float delta = 10.0f / 49.0f;
    const float coeff = -0.5f / (delta * delta);
    #pragma unroll
    for (int g = 0; g < NG; g++) {
        float u = d - (float)g * delta;
        rbf[(size_t)e * NG + g] = expf(coeff * u * u);
    }
}

// ---------------- h init ----------------
__global__ void init_h_kernel(const int* __restrict__ z,
                              const float* __restrict__ emb,
                              float* __restrict__ h) {
    size_t idx = (size_t)blockIdx.x * blockDim.x + threadIdx.x;
    if (idx >= (size_t)NATOMS * NH) return;
    int n = (int)(idx / NH);
    int c = (int)(idx - (size_t)n * NH);
    h[idx] = emb[(size_t)z[n] * NH + c];
}

// ---------------- fp16 tensor-core GEMM, 128x128x16 tile, full-ldmatrix -----
// C[M,N] = A[M,K] @ B[K,N], row-major global (fp32), fp16 smem tiles.
// As: half [m][k] pitch 24 halves; A frags via ldmatrix.x4 (conflict-free).
// Bs: half [k][n] pitch 136 halves; B frags via ldmatrix.x4.trans:
//   one x4.trans = 2 nf tiles x full K=16 (regs: b0/b1 of nf even, b0/b1 of nf odd).
// Global loads: float4, fully coalesced (same pattern as round-11 winner).
// EPI 0: out=v+bias  1: out=ssp(v+bias)  2: out=(v+bias)*rowmul[row]  3: out=v
// EPI 4: acc[row,col] += v+bias  (residual)
#define LDA_H 24
#define LDB_H 136

template<int EPI>
__global__ __launch_bounds__(256, 2)
void gemm_tc(const float* __restrict__ A, const float* __restrict__ Bm,
             const float* __restrict__ bias, float* __restrict__ Cout,
             int M, int Nn, int K,
             const float* __restrict__ rowmul, float* __restrict__ accp)
{
    __shared__ __half As[128 * LDA_H];   // [m][k]
    __shared__ __half Bs[16 * LDB_H];    // [k][n]

    const int tid  = threadIdx.x;
    const int lane = tid & 31;
    const int warp = tid >> 5;
    const int wm = (warp >> 2) * 64;   // 0/64
    const int wn = (warp &  3) * 32;   // 0/32/64/96
    const int g = lane >> 2;
    const int t = lane & 3;
    const int m0 = blockIdx.y * 128;
    const int n0 = blockIdx.x * 128;

    float acc[4][4][4];
    #pragma unroll
    for (int i = 0; i < 4; i++)
        #pragma unroll
        for (int j = 0; j < 4; j++)
            #pragma unroll
            for (int r = 0; r < 4; r++) acc[i][j][r] = 0.0f;

    const bool kvec = ((K & 3) == 0);
    float4 aReg[2], bReg[2];

    auto loadTile = [&](int kt) {
        #pragma unroll
        for (int i = 0; i < 2; i++) {
            int idx = tid + i * 256;
            int m = idx >> 2, t4 = (idx & 3) << 2;
            int row = m0 + m, col = kt + t4;
            float4 v = make_float4(0.f, 0.f, 0.f, 0.f);
            if (row < M) {
                if (kvec && col + 4 <= K) {
                    v = *(const float4*)&A[(size_t)row * K + col];
                } else {
                    const float* ap = &A[(size_t)row * K];
                    if (col + 0 < K) v.x = ap[col + 0];
                    if (col + 1 < K) v.y = ap[col + 1];
                    if (col + 2 < K) v.z = ap[col + 2];
                    if (col + 3 < K) v.w = ap[col + 3];
                }
            }
            aReg[i] = v;
            int k = idx >> 5, n4 = (idx & 31) << 2;
            int brow = kt + k, bcol = n0 + n4;
            float4 w = make_float4(0.f, 0.f, 0.f, 0.f);
            if (brow < K) {
                if (bcol + 4 <= Nn) {
                    w = *(const float4*)&Bm[(size_t)brow * Nn + bcol];
                } else {
                    const float* bp = &Bm[(size_t)brow * Nn];
                    if (bcol + 0 < Nn) w.x = bp[bcol + 0];
                    if (bcol + 1 < Nn) w.y = bp[bcol + 1];
                    if (bcol + 2 < Nn) w.z = bp[bcol + 2];
                    if (bcol + 3 < Nn) w.w = bp[bcol + 3];
                }
            }
            bReg[i] = w;
        }
    };

    auto commitTile = [&]() {
        #pragma unroll
        for (int i = 0; i < 2; i++) {
            int idx = tid + i * 256;
            int m = idx >> 2, t4 = (idx & 3) << 2;
            unsigned pa0 = pack_h2(aReg[i].x, aReg[i].y);
            unsigned pa1 = pack_h2(aReg[i].z, aReg[i].w);
            unsigned* ad = (unsigned*)&As[m * LDA_H + t4];
            ad[0] = pa0; ad[1] = pa1;
            int k = idx >> 5, n4 = (idx & 31) << 2;
            unsigned pb0 = pack_h2(bReg[i].x, bReg[i].y);
            unsigned pb1 = pack_h2(bReg[i].z, bReg[i].w);
            unsigned* bd = (unsigned*)&Bs[k * LDB_H + n4];
            bd[0] = pb0; bd[1] = pb1;
        }
    };

    // A ldmatrix per-lane address: 4 matrices (m0-7,k0-7),(m8-15,k0-7),(m0-7,k8-15),(m8-15,k8-15)
    const int m_lane = wm + ((lane >> 3) & 1) * 8 + (lane & 7);
    const int k_offA = (lane >> 4) * 8;  // halves
    const unsigned aSm = (unsigned)__cvta_generic_to_shared(As);
    const unsigned aLaneAddr = aSm + (unsigned)(m_lane * LDA_H + k_offA) * 2u;
    // B trans-ldmatrix per-lane address: matrix j = (khalf = j&1, nf-sub = j>>1)
    const int bj = lane >> 3, br = lane & 7;
    const unsigned bSm = (unsigned)__cvta_generic_to_shared(Bs);
    const unsigned bLaneAddr = bSm +
        (unsigned)((((bj & 1) * 8 + br) * LDB_H) + wn + ((bj >> 1) * 8)) * 2u;

    loadTile(0);

    for (int k0 = 0; k0 < K; k0 += 16) {
        commitTile();
        __syncthreads();

        int kn = k0 + 16;
        if (kn < K) loadTile(kn);

        // B: 2 x ldmatrix.x4.trans cover 4 nf tiles x K=16
        // bfr[p]: [0]=b0 nf(2p), [1]=b1 nf(2p), [2]=b0 nf(2p+1), [3]=b1 nf(2p+1)
        unsigned bfr[2][4];
        ldm_x4_t(bfr[0], bLaneAddr);
        ldm_x4_t(bfr[1], bLaneAddr + 16u * 2u);

        // A: 4 x ldmatrix.x4, one per mf (full K=16 each)
        unsigned af[4][4];
        #pragma unroll
        for (int mf = 0; mf < 4; mf++)
            ldm_x4(af[mf], aLaneAddr + (unsigned)(mf * 16 * LDA_H) * 2u);

        #pragma unroll
        for (int mf = 0; mf < 4; mf++)
            #pragma unroll
            for (int nf = 0; nf < 4; nf++)
                mma_f16(acc[mf][nf], af[mf],
                        bfr[nf >> 1][(nf & 1) * 2], bfr[nf >> 1][(nf & 1) * 2 + 1]);
        __syncthreads();
    }

    // epilogue
    #pragma unroll
    for (int mf = 0; mf < 4; mf++) {
        #pragma unroll
        for (int nf = 0; nf < 4; nf++) {
            int rb = m0 + wm + mf * 16 + g;
            int cb = n0 + wn + nf * 8 + 2 * t;
            #pragma unroll
            for (int half = 0; half < 2; half++) {
                int mm = rb + half * 8;
                if (mm >= M) continue;
                float v0 = acc[mf][nf][half * 2 + 0];
                float v1 = acc[mf][nf][half * 2 + 1];
                float cm = (EPI == 2) ? rowmul[mm] : 0.0f;
                #pragma unroll
                for (int q = 0; q < 2; q++) {
                    int nn = cb + q;
                    if (nn >= Nn) continue;
                    float v = (q == 0) ? v0 : v1;
                    if (EPI == 0)      { v += bias[nn]; }
                    else if (EPI == 1) { v = ssp(v + bias[nn]); }
                    else if (EPI == 2) { v = (v + bias[nn]) * cm; }
                    else if (EPI == 4) { accp[(size_t)mm * Nn + nn] += v + bias[nn]; continue; }
                    Cout[(size_t)mm * Nn + nn] = v;
                }
            }
        }
    }
}

// ---------------- CFConv scatter (float4 vectorized) ----------------
__global__ void scatter_kernel(const int* __restrict__ ei,
                               const float* __restrict__ hp,
                               const float* __restrict__ W,
                               float* __restrict__ agg) {
    size_t idx = (size_t)blockIdx.x * blockDim.x + threadIdx.x;
    const int Q = NH / 4;  // 150
    if (idx >= (size_t)NEDGES * Q) return;
    int e = (int)(idx / Q);
    int c4 = (int)(idx - (size_t)e * Q) * 4;
    int s = ei[e];
    int t = ei[NEDGES + e];
    float4 hv = *(const float4*)&hp[(size_t)s * NH + c4];
    float4 wv = *(const float4*)&W[(size_t)e * NH + c4];
    float* dst = &agg[(size_t)t * NH + c4];
    atomicAdd(dst + 0, hv.x * wv.x);
    atomicAdd(dst + 1, hv.y * wv.y);
    atomicAdd(dst + 2, hv.z * wv.z);
    atomicAdd(dst + 3, hv.w * wv.w);
}

// ---------------- pooling ----------------
__global__ void pool_sum_kernel(const int* __restrict__ batch,
                                const float* __restrict__ h,
                                float* __restrict__ psum) {
    size_t idx = (size_t)blockIdx.x * blockDim.x + threadIdx.x;
    const int Q = NH / 4;
    if (idx >= (size_t)NATOMS * Q) return;
    int n = (int)(idx / Q);
    int c4 = (int)(idx - (size_t)n * Q) * 4;
    float4 hv = *(const float4*)&h[(size_t)n * NH + c4];
    float* dst = &psum[(size_t)batch[n] * NH + c4];
    atomicAdd(dst + 0, hv.x);
    atomicAdd(dst + 1, hv.y);
    atomicAdd(dst + 2, hv.z);
    atomicAdd(dst + 3, hv.w);
}

__global__ void pool_cnt_kernel(const int* __restrict__ batch, float* __restrict__ cnt) {
    int n = blockIdx.x * blockDim.x + threadIdx.x;
    if (n >= NATOMS) return;
    atomicAdd(&cnt[batch[n]], 1.0f);
}

__global__ void pool_div_kernel(float* __restrict__ psum, const float* __restrict__ cnt) {
    int idx = blockIdx.x * blockDim.x + threadIdx.x;
    if (idx >= NB * NH) return;
    int b = idx / NH;
    psum[idx] /= fmaxf(cnt[b], 1.0f);
}

// ---------------- host launcher ----------------
extern "C" void kernel_launch(void* const* d_in, const int* in_sizes, int n_in,
                              void* d_out, int out_size) {
    const int*   z        = (const int*)  d_in[0];
    const float* pos      = (const float*)d_in[1];
    const int*   batch    = (const int*)  d_in[2];
    const int*   ei       = (const int*)  d_in[3];
    const float* emb      = (const float*)d_in[4];
    const float* mlp_w1   = (const float*)d_in[5];
    const float* mlp_b1   = (const float*)d_in[6];
    const float* mlp_w2   = (const float*)d_in[7];
    const float* mlp_b2   = (const float*)d_in[8];
    const float* lin1_w   = (const float*)d_in[9];
    const float* lin2_w   = (const float*)d_in[10];
    const float* lin2_b   = (const float*)d_in[11];
    const float* int_lin_w = (const float*)d_in[12];
    const float* int_lin_b = (const float*)d_in[13];
    const float* pool_w   = (const float*)d_in[14];
    const float* pool_b   = (const float*)d_in[15];
    float* out = (float*)d_out;

    float *p_rbf, *p_C, *p_h, *p_t1, *p_W, *p_hp, *p_agg, *p_x, *p_pool, *p_cnt;
    cudaGetSymbolAddress((void**)&p_rbf,  g_rbf);
    cudaGetSymbolAddress((void**)&p_C,    g_Ccut);
    cudaGetSymbolAddress((void**)&p_h,    g_h);
    cudaGetSymbolAddress((void**)&p_t1,   g_t1);
    cudaGetSymbolAddress((void**)&p_W,    g_W);
    cudaGetSymbolAddress((void**)&p_hp,   g_hp);
    cudaGetSymbolAddress((void**)&p_agg,  g_agg);
    cudaGetSymbolAddress((void**)&p_x,    g_x);
    cudaGetSymbolAddress((void**)&p_pool, g_pool);
    cudaGetSymbolAddress((void**)&p_cnt,  g_cnt);

    edge_geom_kernel<<<(NEDGES + 255) / 256, 256>>>(pos, ei, p_rbf, p_C);
    {
        size_t tot = (size_t)NATOMS * NH;
        init_h_kernel<<<(unsigned)((tot + 255) / 256), 256>>>(z, emb, p_h);
    }

    dim3 blk(256);
    dim3 gE((NH + 127) / 128, (NEDGES + 127) / 128);
    dim3 gN((NH + 127) / 128, (NATOMS + 127) / 128);
    dim3 gB((NH + 127) / 128, (NB + 127) / 128);

    for (int k = 0; k < NL; k++) {
        const float* w1  = mlp_w1 + (size_t)k * NG * NH;
        const float* b1  = mlp_b1 + (size_t)k * NH;
        const float* w2  = mlp_w2 + (size_t)k * NH * NH;
        const float* b2  = mlp_b2 + (size_t)k * NH;
        const float* l1  = lin1_w + (size_t)k * NH * NH;
        const float* l2  = lin2_w + (size_t)k * NH * NH;
        const float* l2b = lin2_b + (size_t)k * NH;
        const float* il  = int_lin_w + (size_t)k * NH * NH;
        const float* ilb = int_lin_b + (size_t)k * NH;

        // t1 = ssp(rbf @ w1 + b1)           [E,H]
        gemm_tc<1><<<gE, blk>>>(p_rbf, w1, b1, p_t1, NEDGES, NH, NG, nullptr, nullptr);
        // W = (t1 @ w2 + b2) * C[:,None]    [E,H]
        gemm_tc<2><<<gE, blk>>>(p_t1, w2, b2, p_W, NEDGES, NH, NH, p_C, nullptr);
        // hp = h @ lin1                     [N,H]
        gemm_tc<3><<<gN, blk>>>(p_h, l1, nullptr, p_hp, NATOMS, NH, NH, nullptr, nullptr);
        // agg = scatter_add(hp[src] * W, dst)
        cudaMemsetAsync(p_agg, 0, (size_t)NATOMS * NH * sizeof(float));
        {
            size_t tot = (size_t)NEDGES * (NH / 4);
            scatter_kernel<<<(unsigned)((tot + 255) / 256), 256>>>(ei, p_hp, p_W, p_agg);
        }
        // x = ssp(agg @ lin2 + lin2_b)      [N,H]
        gemm_tc<1><<<gN, blk>>>(p_agg, l2, l2b, p_x, NATOMS, NH, NH, nullptr, nullptr);
        // h += x @ int_lin + int_lin_b      [N,H]
        gemm_tc<4><<<gN, blk>>>(p_x, il, ilb, nullptr, NATOMS, NH, NH, nullptr, p_h);
    }

    cudaMemsetAsync(p_pool, 0, (size_t)NB * NH * sizeof(float));
    cudaMemsetAsync(p_cnt, 0, NB * sizeof(float));
    {
        size_t tot = (size_t)NATOMS * (NH / 4);
        pool_sum_kernel<<<(unsigned)((tot + 255) / 256), 256>>>(batch, p_h, p_pool);
    }
    pool_cnt_kernel<<<(NATOMS + 255) / 256, 256>>>(batch, p_cnt);
    pool_div_kernel<<<(NB * NH + 255) / 256, 256>>>(p_pool, p_cnt);

    // out = pooled @ pool_w + pool_b       [B,H]
    gemm_tc<0><<<gB, blk>>>(p_pool, pool_w, pool_b, out, NB, NH, NH, nullptr, nullptr);
}